// round 11
// baseline (speedup 1.0000x reference)
#include <cuda_runtime.h>
#include <cuda_fp16.h>
#include <cstdint>
#include <cstddef>
#include <cstring>

// ============================================================================
// TTLinear, fully fused single launch (R11 = R10 with 16 warps):
//   CTA = 64-row b-block, 512 threads. xT (64x1024 fp16) loaded once into
//   registers (64/thread across 16 warps). Loop over 16 iterations x 4 m01
//   planes, single 128KB Z buffer:
//     stage1: Zs[bl][k=n23*8+r2] = xT x P(m01)   (4 planes -> smem)
//     sync; stage2: y = Zs x Q^T + bias (32x32 warp tiles); sync.
// ============================================================================

#define OUTF 4096
#define P_OFF  0u
#define Q_OFF  32768u
#define ZX_OFF 65536u              // xT overlay during init; then 4x32KB Z
#define SMEM_TOTAL 196608

#define SW(o) ((o) ^ ((((o) >> 7) & 3u) << 4))

static __device__ __forceinline__ uint32_t h2u(__half2 h) {
    uint32_t u; memcpy(&u, &h, 4); return u;
}
static __device__ __forceinline__ uint32_t s2u(const void* p) {
    uint32_t a;
    asm("{ .reg .u64 t; cvta.to.shared.u64 t, %1; cvt.u32.u64 %0, t; }" : "=r"(a) : "l"(p));
    return a;
}
// 512B rows with per-row XOR swizzle (conflict-free STS + ldmatrix)
static __device__ __forceinline__ uint32_t zsw(int row, uint32_t off) {
    return (uint32_t)(row * 512) + (off ^ (((uint32_t)row & 7u) << 4));
}
static __device__ __forceinline__ void ldm_x4(uint32_t* r, uint32_t addr) {
    asm volatile("ldmatrix.sync.aligned.m8n8.x4.shared.b16 {%0,%1,%2,%3}, [%4];"
                 : "=r"(r[0]), "=r"(r[1]), "=r"(r[2]), "=r"(r[3]) : "r"(addr));
}
static __device__ __forceinline__ void mma16816(float* d, const uint32_t* a,
                                                const uint32_t* b) {
    asm volatile(
        "mma.sync.aligned.m16n8k16.row.col.f32.f16.f16.f32 "
        "{%0,%1,%2,%3}, {%4,%5,%6,%7}, {%8,%9}, {%0,%1,%2,%3};"
        : "+f"(d[0]), "+f"(d[1]), "+f"(d[2]), "+f"(d[3])
        : "r"(a[0]), "r"(a[1]), "r"(a[2]), "r"(a[3]), "r"(b[0]), "r"(b[1]));
}

__global__ void __launch_bounds__(512, 1)
k_fused(const float* __restrict__ x,
        const float* __restrict__ c0, const float* __restrict__ c1,
        const float* __restrict__ c2, const float* __restrict__ c3,
        const float* __restrict__ bias, float* __restrict__ out)
{
    extern __shared__ char smem[];
    const uint32_t sbu = s2u(smem);
    const int tid  = threadIdx.x;
    const int lane = tid & 31;
    const int w    = tid >> 5;                      // 0..15
    const int quad = lane >> 3, lr = lane & 7;
    const int b0   = blockIdx.x * 64;

    // ---- build P[(m01*8+r2)][n01] fp16, 64B SW rows ----
#pragma unroll
    for (int i = 0; i < 32; ++i) {
        int idx = tid + i * 512;                    // 16384
        int n01 = idx & 31, row = idx >> 5;         // row = m01*8+r2
        int r2 = row & 7, m01 = row >> 3;
        int m0 = m01 >> 3, m1 = m01 & 7, n0 = n01 >> 3, n1 = n01 & 7;
        float s = 0.f;
#pragma unroll
        for (int r1 = 0; r1 < 8; ++r1)
            s = fmaf(c0[m0 * 32 + r1 * 4 + n0], c1[r1 * 512 + m1 * 64 + r2 * 8 + n1], s);
        *(__half*)(smem + P_OFF + SW((uint32_t)(row * 64 + n01 * 2))) = __float2half_rn(s);
    }
    // ---- build Q[m23][k=n23*8+r2] fp16, 512B zsw rows ----
#pragma unroll
    for (int i = 0; i < 32; ++i) {
        int idx = tid + i * 512;                    // 16384
        int k = idx & 255, m23 = idx >> 8;
        int r2 = k & 7, n23 = k >> 3;
        int m2 = m23 >> 3, m3 = m23 & 7, n2 = n23 >> 2, n3 = n23 & 3;
        float s = 0.f;
#pragma unroll
        for (int r3 = 0; r3 < 8; ++r3)
            s = fmaf(c2[r2 * 512 + m2 * 64 + r3 * 8 + n2], c3[r3 * 32 + m3 * 4 + n3], s);
        *(__half*)(smem + Q_OFF + zsw(m23, (uint32_t)(k * 2))) = __float2half_rn(s);
    }
    // ---- xT fill: rows R = n23*64 + bl, 2048 x 64B SW rows (overlay on Z) ----
    {
        const float4* x4 = (const float4*)x;
        const int row = tid >> 3;                   // local b, 0..63
        const int qb  = tid & 7;
#pragma unroll
        for (int i = 0; i < 32; ++i) {
            int q = qb + i * 8;                     // 0..255
            float4 f = x4[(size_t)(b0 + row) * 256 + q];
            int n01 = q >> 3;
            int n23b = (q & 7) * 4;
            float v[4] = { f.x, f.y, f.z, f.w };
#pragma unroll
            for (int j = 0; j < 4; ++j) {
                uint32_t R = (uint32_t)((n23b + j) * 64 + row);
                *(__half*)(smem + ZX_OFF + SW(R * 64u + (uint32_t)(n01 * 2)))
                    = __float2half_rn(v[j]);
            }
        }
    }
    __syncthreads();

    // ---- stage-1 A cache: warp w owns xT rows [w*128, w*128+128) ----
    uint32_t ac[8][2][4];
#pragma unroll
    for (int mt = 0; mt < 8; ++mt)
#pragma unroll
        for (int kk = 0; kk < 2; ++kk)
            ldm_x4(ac[mt][kk], sbu + ZX_OFF
                   + SW((uint32_t)((w * 128 + mt * 16 + (quad & 1) * 8 + lr) * 64
                                   + kk * 32 + ((quad >> 1) & 1) * 16)));
    __syncthreads();                                // xT consumed

    // stage2 warp grid: 2(b halves) x 8(32-col groups over 4 planes)
    const int wm2 = w >> 3;                         // 0..1
    const int wn2 = w & 7;                          // 0..7
    const int plane_sel = wn2 >> 1;                 // 0..3
    const int colhalf = wn2 & 1;                    // 0..1
    const int s2brow = wm2 * 32;

    float d2[2][4][4];
#pragma unroll
    for (int i = 0; i < 2; ++i)
#pragma unroll
        for (int j = 0; j < 4; ++j)
#pragma unroll
            for (int q = 0; q < 4; ++q) d2[i][j][q] = 0.f;

    for (int it = 0; it < 16; ++it) {
        // ---- stage1: 4 planes into Z ----
#pragma unroll
        for (int pp = 0; pp < 4; ++pp) {
            int m01 = it * 4 + pp;
            uint32_t bfP[4];
            ldm_x4(bfP, sbu + P_OFF + SW((uint32_t)((m01 * 8 + lr) * 64 + quad * 16)));
            uint32_t zpb = ZX_OFF + (uint32_t)(pp * 32768);
#pragma unroll
            for (int mt = 0; mt < 8; ++mt) {
                float acc[4] = {0.f, 0.f, 0.f, 0.f};
                mma16816(acc, ac[mt][0], &bfP[0]);
                mma16816(acc, ac[mt][1], &bfP[2]);
                int Rb = w * 128 + mt * 16 + (lane >> 2);
#pragma unroll
                for (int half = 0; half < 2; ++half) {
                    int R = Rb + half * 8;
                    int n23 = R >> 6, bl = R & 63;
                    __half2 v = __floats2half2_rn(acc[half * 2], acc[half * 2 + 1]);
                    *(uint32_t*)(smem + zpb
                        + zsw(bl, (uint32_t)(n23 * 16 + (lane & 3) * 4))) = h2u(v);
                }
            }
        }
        __syncthreads();                            // Z ready

        // ---- stage2: y[64 x 256] (4 planes) ----
        const uint32_t za = sbu + ZX_OFF + (uint32_t)(plane_sel * 32768);
#pragma unroll
        for (int ks = 0; ks < 16; ++ks) {
            uint32_t a[2][4], bq[2][4];
#pragma unroll
            for (int mt = 0; mt < 2; ++mt)
                ldm_x4(a[mt], za + zsw(s2brow + mt * 16 + (lane & 15),
                                       (uint32_t)(ks * 32 + (lane >> 4) * 16)));
#pragma unroll
            for (int nt = 0; nt < 2; ++nt)
                ldm_x4(bq[nt], sbu + Q_OFF
                       + zsw(colhalf * 32 + nt * 16 + ((quad >> 1) & 1) * 8 + lr,
                             (uint32_t)(ks * 32 + (quad & 1) * 16)));
#pragma unroll
            for (int mt = 0; mt < 2; ++mt)
#pragma unroll
                for (int nt = 0; nt < 2; ++nt) {
                    mma16816(d2[mt][nt * 2],     a[mt], &bq[nt][0]);
                    mma16816(d2[mt][nt * 2 + 1], a[mt], &bq[nt][2]);
                }
        }

        // ---- epilogue: +bias, write fp32; reset accumulators ----
        const int m01 = it * 4 + plane_sel;
        const int erow  = b0 + s2brow + (lane >> 2);
        const int ecolb = m01 * 64 + colhalf * 32 + (lane & 3) * 2;
#pragma unroll
        for (int mt = 0; mt < 2; ++mt) {
#pragma unroll
            for (int nt = 0; nt < 2; ++nt) {
#pragma unroll
                for (int p = 0; p < 2; ++p) {
                    int col = ecolb + nt * 16 + p * 8;
                    float bx = __ldg(bias + col);
                    float by = __ldg(bias + col + 1);
                    float* r0 = out + (size_t)(erow + mt * 16) * OUTF + col;
                    float* r1 = r0 + 8 * OUTF;
                    float* dd = d2[mt][nt * 2 + p];
                    float2 v0 = { dd[0] + bx, dd[1] + by };
                    float2 v1 = { dd[2] + bx, dd[3] + by };
                    *reinterpret_cast<float2*>(r0) = v0;
                    *reinterpret_cast<float2*>(r1) = v1;
                    dd[0] = dd[1] = dd[2] = dd[3] = 0.f;
                }
            }
        }
        __syncthreads();                            // Z reusable
    }
}

// ============================================================================
extern "C" void kernel_launch(void* const* d_in, const int* in_sizes, int n_in,
                              void* d_out, int out_size)
{
    const float* x    = (const float*)d_in[0];
    const float* c0   = (const float*)d_in[1];
    const float* c1   = (const float*)d_in[2];
    const float* c2   = (const float*)d_in[3];
    const float* c3   = (const float*)d_in[4];
    const float* bias = (const float*)d_in[5];
    float* out = (float*)d_out;

    cudaFuncSetAttribute(k_fused, cudaFuncAttributeMaxDynamicSharedMemorySize,
                         SMEM_TOTAL);
    k_fused<<<128, 512, SMEM_TOTAL>>>(x, c0, c1, c2, c3, bias, out);
}

// round 12
// speedup vs baseline: 1.0177x; 1.0177x over previous
#include <cuda_runtime.h>
#include <cuda_fp16.h>
#include <cstdint>
#include <cstddef>
#include <cstring>

// ============================================================================
// TTLinear, fully fused single launch (R12 = R10 + manual stage1/stage2
// interleave + bias in smem):
//   CTA = 64-row b-block, 256 threads. xT (64x1024 fp16) cached in registers.
//   Iteration it: stage1 produces planes 2(it+1),2(it+1)+1 into Z buf (it+1)&1
//   INTERLEAVED with stage2 consuming planes 2it,2it+1 from Z buf it&1.
//   Interleave puts stage1 HMMA work under stage2 ldmatrix latency, so the
//   tensor and L1 pipes (each ~45us busy, previously serial) overlap.
// ============================================================================

#define OUTF 4096
#define P_OFF    0u
#define Q_OFF    32768u
#define ZX_OFF   65536u            // xT overlay during init; then 2x64KB Z
#define BIAS_OFF 196608u
#define SMEM_TOTAL 212992

#define SW(o) ((o) ^ ((((o) >> 7) & 3u) << 4))

static __device__ __forceinline__ uint32_t h2u(__half2 h) {
    uint32_t u; memcpy(&u, &h, 4); return u;
}
static __device__ __forceinline__ uint32_t s2u(const void* p) {
    uint32_t a;
    asm("{ .reg .u64 t; cvta.to.shared.u64 t, %1; cvt.u32.u64 %0, t; }" : "=r"(a) : "l"(p));
    return a;
}
// 512B rows with per-row XOR swizzle (conflict-free STS + ldmatrix)
static __device__ __forceinline__ uint32_t zsw(int row, uint32_t off) {
    return (uint32_t)(row * 512) + (off ^ (((uint32_t)row & 7u) << 4));
}
static __device__ __forceinline__ void ldm_x4(uint32_t* r, uint32_t addr) {
    asm volatile("ldmatrix.sync.aligned.m8n8.x4.shared.b16 {%0,%1,%2,%3}, [%4];"
                 : "=r"(r[0]), "=r"(r[1]), "=r"(r[2]), "=r"(r[3]) : "r"(addr));
}
static __device__ __forceinline__ void mma16816(float* d, const uint32_t* a,
                                                const uint32_t* b) {
    asm volatile(
        "mma.sync.aligned.m16n8k16.row.col.f32.f16.f16.f32 "
        "{%0,%1,%2,%3}, {%4,%5,%6,%7}, {%8,%9}, {%0,%1,%2,%3};"
        : "+f"(d[0]), "+f"(d[1]), "+f"(d[2]), "+f"(d[3])
        : "r"(a[0]), "r"(a[1]), "r"(a[2]), "r"(a[3]), "r"(b[0]), "r"(b[1]));
}

__global__ void __launch_bounds__(256, 1)
k_fused(const float* __restrict__ x,
        const float* __restrict__ c0, const float* __restrict__ c1,
        const float* __restrict__ c2, const float* __restrict__ c3,
        const float* __restrict__ bias, float* __restrict__ out)
{
    extern __shared__ char smem[];
    const uint32_t sbu = s2u(smem);
    const int tid  = threadIdx.x;
    const int lane = tid & 31;
    const int w    = tid >> 5;                      // 0..7
    const int quad = lane >> 3, lr = lane & 7;
    const int b0   = blockIdx.x * 64;

    // ---- build P[(m01*8+r2)][n01] fp16, 64B SW rows ----
#pragma unroll
    for (int i = 0; i < 64; ++i) {
        int idx = tid + i * 256;                    // 16384
        int n01 = idx & 31, row = idx >> 5;         // row = m01*8+r2
        int r2 = row & 7, m01 = row >> 3;
        int m0 = m01 >> 3, m1 = m01 & 7, n0 = n01 >> 3, n1 = n01 & 7;
        float s = 0.f;
#pragma unroll
        for (int r1 = 0; r1 < 8; ++r1)
            s = fmaf(c0[m0 * 32 + r1 * 4 + n0], c1[r1 * 512 + m1 * 64 + r2 * 8 + n1], s);
        *(__half*)(smem + P_OFF + SW((uint32_t)(row * 64 + n01 * 2))) = __float2half_rn(s);
    }
    // ---- build Q[m23][k=n23*8+r2] fp16, 512B zsw rows ----
#pragma unroll
    for (int i = 0; i < 64; ++i) {
        int idx = tid + i * 256;                    // 16384
        int k = idx & 255, m23 = idx >> 8;
        int r2 = k & 7, n23 = k >> 3;
        int m2 = m23 >> 3, m3 = m23 & 7, n2 = n23 >> 2, n3 = n23 & 3;
        float s = 0.f;
#pragma unroll
        for (int r3 = 0; r3 < 8; ++r3)
            s = fmaf(c2[r2 * 512 + m2 * 64 + r3 * 8 + n2], c3[r3 * 32 + m3 * 4 + n3], s);
        *(__half*)(smem + Q_OFF + zsw(m23, (uint32_t)(k * 2))) = __float2half_rn(s);
    }
    // ---- bias -> smem ----
    {
        const float4* b4 = (const float4*)bias;
        float4* sb4 = (float4*)(smem + BIAS_OFF);
#pragma unroll
        for (int i = 0; i < 4; ++i)
            sb4[tid + i * 256] = b4[tid + i * 256];
    }
    // ---- xT fill: rows R = n23*64 + bl, 2048 x 64B SW rows (overlay on Z) ----
    {
        const float4* x4 = (const float4*)x;
        const int row = tid >> 2;                   // local b, 0..63
        const int qb  = tid & 3;
#pragma unroll
        for (int i = 0; i < 64; ++i) {
            int q = qb + i * 4;                     // 0..255
            float4 f = x4[(size_t)(b0 + row) * 256 + q];
            int n01 = q >> 3;
            int n23b = (q & 7) * 4;
            float v[4] = { f.x, f.y, f.z, f.w };
#pragma unroll
            for (int j = 0; j < 4; ++j) {
                uint32_t R = (uint32_t)((n23b + j) * 64 + row);
                *(__half*)(smem + ZX_OFF + SW(R * 64u + (uint32_t)(n01 * 2)))
                    = __float2half_rn(v[j]);
            }
        }
    }
    __syncthreads();

    // ---- stage-1 A cache: warp w owns xT rows [w*256, w*256+256) ----
    uint32_t ac[16][2][4];
#pragma unroll
    for (int mt = 0; mt < 16; ++mt)
#pragma unroll
        for (int kk = 0; kk < 2; ++kk)
            ldm_x4(ac[mt][kk], sbu + ZX_OFF
                   + SW((uint32_t)((w * 256 + mt * 16 + (quad & 1) * 8 + lr) * 64
                                   + kk * 32 + ((quad >> 1) & 1) * 16)));
    __syncthreads();                                // xT consumed

    // stage2 warp mapping: 2(b halves) x 2(planes) x 2(col halves)
    const int wm2 = w >> 2;                         // 0..1
    const int wn2 = w & 3;
    const int plane_sel = wn2 >> 1;                 // 0..1
    const int colhalf = wn2 & 1;                    // 0..1
    const int s2brow = wm2 * 32;

    float d2[2][4][4];
#pragma unroll
    for (int i = 0; i < 2; ++i)
#pragma unroll
        for (int j = 0; j < 4; ++j)
#pragma unroll
            for (int q = 0; q < 4; ++q) d2[i][j][q] = 0.f;

    // ---- prologue: full stage1 for iteration 0 (planes 0,1 -> buffer 0) ----
    {
#pragma unroll
        for (int pp = 0; pp < 2; ++pp) {
            uint32_t bfP[4];
            ldm_x4(bfP, sbu + P_OFF + SW((uint32_t)((pp * 8 + lr) * 64 + quad * 16)));
            uint32_t zpb = ZX_OFF + (uint32_t)(pp * 32768);
#pragma unroll
            for (int mt = 0; mt < 16; ++mt) {
                float acc[4] = {0.f, 0.f, 0.f, 0.f};
                mma16816(acc, ac[mt][0], &bfP[0]);
                mma16816(acc, ac[mt][1], &bfP[2]);
                int Rb = w * 256 + mt * 16 + (lane >> 2);
#pragma unroll
                for (int half = 0; half < 2; ++half) {
                    int R = Rb + half * 8;
                    int n23 = R >> 6, bl = R & 63;
                    __half2 v = __floats2half2_rn(acc[half * 2], acc[half * 2 + 1]);
                    *(uint32_t*)(smem + zpb
                        + zsw(bl, (uint32_t)(n23 * 16 + (lane & 3) * 4))) = h2u(v);
                }
            }
        }
    }

    for (int it = 0; it < 32; ++it) {
        __syncthreads();                            // Z[it&1] visible
        const int prod = it + 1;                    // planes produced this iter
        const bool do_prod = (prod < 32);

        uint32_t bfP[2][4];
        if (do_prod) {
#pragma unroll
            for (int pp = 0; pp < 2; ++pp)
                ldm_x4(bfP[pp], sbu + P_OFF
                       + SW((uint32_t)(((prod * 2 + pp) * 8 + lr) * 64 + quad * 16)));
        }

        const uint32_t za = sbu + ZX_OFF + (uint32_t)((it & 1) * 65536)
                          + (uint32_t)(plane_sel * 32768);
        const uint32_t zb = ZX_OFF + (uint32_t)(((it + 1) & 1) * 65536);

        // ---- interleaved body: 16 steps ----
#pragma unroll
        for (int j = 0; j < 16; ++j) {
            // stage2 loads for ks=j (consume buffer it&1)
            uint32_t a[2][4], bq[2][4];
#pragma unroll
            for (int mt = 0; mt < 2; ++mt)
                ldm_x4(a[mt], za + zsw(s2brow + mt * 16 + (lane & 15),
                                       (uint32_t)(j * 32 + (lane >> 4) * 16)));
#pragma unroll
            for (int nt = 0; nt < 2; ++nt)
                ldm_x4(bq[nt], sbu + Q_OFF
                       + zsw(colhalf * 32 + nt * 16 + ((quad >> 1) & 1) * 8 + lr,
                             (uint32_t)(j * 32 + (quad & 1) * 16)));

            // stage1 slice: plane pp=j>>3, mt pair (fills buffer (it+1)&1)
            if (do_prod) {
                const int pp = j >> 3;
                const uint32_t zpb = zb + (uint32_t)(pp * 32768);
#pragma unroll
                for (int t = 0; t < 2; ++t) {
                    const int mtt = (j & 7) * 2 + t;
                    float acc[4] = {0.f, 0.f, 0.f, 0.f};
                    mma16816(acc, ac[mtt][0], &bfP[pp][0]);
                    mma16816(acc, ac[mtt][1], &bfP[pp][2]);
                    int Rb = w * 256 + mtt * 16 + (lane >> 2);
#pragma unroll
                    for (int half = 0; half < 2; ++half) {
                        int R = Rb + half * 8;
                        int n23 = R >> 6, bl = R & 63;
                        __half2 v = __floats2half2_rn(acc[half * 2], acc[half * 2 + 1]);
                        *(uint32_t*)(smem + zpb
                            + zsw(bl, (uint32_t)(n23 * 16 + (lane & 3) * 4))) = h2u(v);
                    }
                }
            }

            // stage2 MMAs for ks=j
#pragma unroll
            for (int mt = 0; mt < 2; ++mt)
#pragma unroll
                for (int nt = 0; nt < 2; ++nt) {
                    mma16816(d2[mt][nt * 2],     a[mt], &bq[nt][0]);
                    mma16816(d2[mt][nt * 2 + 1], a[mt], &bq[nt][2]);
                }
        }

        // ---- epilogue: +bias (smem), write fp32; reset accumulators ----
        const int m01 = it * 2 + plane_sel;
        const int erow  = b0 + s2brow + (lane >> 2);
        const int ecolb = m01 * 64 + colhalf * 32 + (lane & 3) * 2;
#pragma unroll
        for (int mt = 0; mt < 2; ++mt) {
#pragma unroll
            for (int nt = 0; nt < 2; ++nt) {
#pragma unroll
                for (int p = 0; p < 2; ++p) {
                    int col = ecolb + nt * 16 + p * 8;
                    float2 bv = *(const float2*)(smem + BIAS_OFF + col * 4);
                    float* r0 = out + (size_t)(erow + mt * 16) * OUTF + col;
                    float* r1 = r0 + 8 * OUTF;
                    float* dd = d2[mt][nt * 2 + p];
                    float2 v0 = { dd[0] + bv.x, dd[1] + bv.y };
                    float2 v1 = { dd[2] + bv.x, dd[3] + bv.y };
                    *reinterpret_cast<float2*>(r0) = v0;
                    *reinterpret_cast<float2*>(r1) = v1;
                    dd[0] = dd[1] = dd[2] = dd[3] = 0.f;
                }
            }
        }
    }
}

// ============================================================================
extern "C" void kernel_launch(void* const* d_in, const int* in_sizes, int n_in,
                              void* d_out, int out_size)
{
    const float* x    = (const float*)d_in[0];
    const float* c0   = (const float*)d_in[1];
    const float* c1   = (const float*)d_in[2];
    const float* c2   = (const float*)d_in[3];
    const float* c3   = (const float*)d_in[4];
    const float* bias = (const float*)d_in[5];
    float* out = (float*)d_out;

    cudaFuncSetAttribute(k_fused, cudaFuncAttributeMaxDynamicSharedMemorySize,
                         SMEM_TOTAL);
    k_fused<<<128, 256, SMEM_TOTAL>>>(x, c0, c1, c2, c3, bias, out);
}

// round 13
// speedup vs baseline: 1.1471x; 1.1271x over previous
#include <cuda_runtime.h>
#include <cuda_fp16.h>
#include <cstdint>
#include <cstddef>
#include <cstring>

// ============================================================================
// TTLinear, fully fused single launch (R13 = R10 with 4 planes/iteration and
// stage-2 warp tiles 64x32 to kill Q-fragment duplication):
//   CTA = 64-row b-block, 256 threads, xT cached in registers (128/thread).
//   Iteration: stage1 fills 4 m01 planes into a single 128KB Z buffer; sync;
//   each warp runs stage2 on its own (plane, 32-col half) with a 64x32 tile;
//   sync. smem traffic/plane: 128KB (was 160KB in R10).
// ============================================================================

#define OUTF 4096
#define P_OFF  0u
#define Q_OFF  32768u
#define ZX_OFF 65536u              // xT overlay during init; then 4x32KB Z
#define SMEM_TOTAL 196608

#define SW(o) ((o) ^ ((((o) >> 7) & 3u) << 4))

static __device__ __forceinline__ uint32_t h2u(__half2 h) {
    uint32_t u; memcpy(&u, &h, 4); return u;
}
static __device__ __forceinline__ uint32_t s2u(const void* p) {
    uint32_t a;
    asm("{ .reg .u64 t; cvta.to.shared.u64 t, %1; cvt.u32.u64 %0, t; }" : "=r"(a) : "l"(p));
    return a;
}
// 512B rows with per-row XOR swizzle (conflict-free STS + ldmatrix)
static __device__ __forceinline__ uint32_t zsw(int row, uint32_t off) {
    return (uint32_t)(row * 512) + (off ^ (((uint32_t)row & 7u) << 4));
}
static __device__ __forceinline__ void ldm_x4(uint32_t* r, uint32_t addr) {
    asm volatile("ldmatrix.sync.aligned.m8n8.x4.shared.b16 {%0,%1,%2,%3}, [%4];"
                 : "=r"(r[0]), "=r"(r[1]), "=r"(r[2]), "=r"(r[3]) : "r"(addr));
}
static __device__ __forceinline__ void mma16816(float* d, const uint32_t* a,
                                                const uint32_t* b) {
    asm volatile(
        "mma.sync.aligned.m16n8k16.row.col.f32.f16.f16.f32 "
        "{%0,%1,%2,%3}, {%4,%5,%6,%7}, {%8,%9}, {%0,%1,%2,%3};"
        : "+f"(d[0]), "+f"(d[1]), "+f"(d[2]), "+f"(d[3])
        : "r"(a[0]), "r"(a[1]), "r"(a[2]), "r"(a[3]), "r"(b[0]), "r"(b[1]));
}

__global__ void __launch_bounds__(256, 1)
k_fused(const float* __restrict__ x,
        const float* __restrict__ c0, const float* __restrict__ c1,
        const float* __restrict__ c2, const float* __restrict__ c3,
        const float* __restrict__ bias, float* __restrict__ out)
{
    extern __shared__ char smem[];
    const uint32_t sbu = s2u(smem);
    const int tid  = threadIdx.x;
    const int lane = tid & 31;
    const int w    = tid >> 5;                      // 0..7
    const int quad = lane >> 3, lr = lane & 7;
    const int b0   = blockIdx.x * 64;

    // ---- build P[(m01*8+r2)][n01] fp16, 64B SW rows ----
#pragma unroll
    for (int i = 0; i < 64; ++i) {
        int idx = tid + i * 256;                    // 16384
        int n01 = idx & 31, row = idx >> 5;         // row = m01*8+r2
        int r2 = row & 7, m01 = row >> 3;
        int m0 = m01 >> 3, m1 = m01 & 7, n0 = n01 >> 3, n1 = n01 & 7;
        float s = 0.f;
#pragma unroll
        for (int r1 = 0; r1 < 8; ++r1)
            s = fmaf(c0[m0 * 32 + r1 * 4 + n0], c1[r1 * 512 + m1 * 64 + r2 * 8 + n1], s);
        *(__half*)(smem + P_OFF + SW((uint32_t)(row * 64 + n01 * 2))) = __float2half_rn(s);
    }
    // ---- build Q[m23][k=n23*8+r2] fp16, 512B zsw rows ----
#pragma unroll
    for (int i = 0; i < 64; ++i) {
        int idx = tid + i * 256;                    // 16384
        int k = idx & 255, m23 = idx >> 8;
        int r2 = k & 7, n23 = k >> 3;
        int m2 = m23 >> 3, m3 = m23 & 7, n2 = n23 >> 2, n3 = n23 & 3;
        float s = 0.f;
#pragma unroll
        for (int r3 = 0; r3 < 8; ++r3)
            s = fmaf(c2[r2 * 512 + m2 * 64 + r3 * 8 + n2], c3[r3 * 32 + m3 * 4 + n3], s);
        *(__half*)(smem + Q_OFF + zsw(m23, (uint32_t)(k * 2))) = __float2half_rn(s);
    }
    // ---- xT fill: rows R = n23*64 + bl, 2048 x 64B SW rows (overlay on Z) ----
    {
        const float4* x4 = (const float4*)x;
        const int row = tid >> 2;                   // local b, 0..63
        const int qb  = tid & 3;
#pragma unroll
        for (int i = 0; i < 64; ++i) {
            int q = qb + i * 4;                     // 0..255
            float4 f = x4[(size_t)(b0 + row) * 256 + q];
            int n01 = q >> 3;
            int n23b = (q & 7) * 4;
            float v[4] = { f.x, f.y, f.z, f.w };
#pragma unroll
            for (int j = 0; j < 4; ++j) {
                uint32_t R = (uint32_t)((n23b + j) * 64 + row);
                *(__half*)(smem + ZX_OFF + SW(R * 64u + (uint32_t)(n01 * 2)))
                    = __float2half_rn(v[j]);
            }
        }
    }
    __syncthreads();

    // ---- stage-1 A cache: warp w owns xT rows [w*256, w*256+256) ----
    uint32_t ac[16][2][4];
#pragma unroll
    for (int mt = 0; mt < 16; ++mt)
#pragma unroll
        for (int kk = 0; kk < 2; ++kk)
            ldm_x4(ac[mt][kk], sbu + ZX_OFF
                   + SW((uint32_t)((w * 256 + mt * 16 + (quad & 1) * 8 + lr) * 64
                                   + kk * 32 + ((quad >> 1) & 1) * 16)));
    __syncthreads();                                // xT consumed

    // stage2 warp mapping: plane = w&3 (of 4 per iter), colhalf = w>>2
    const int plane_sel = w & 3;
    const int colhalf   = w >> 2;

    float d2[4][4][4];
#pragma unroll
    for (int i = 0; i < 4; ++i)
#pragma unroll
        for (int j = 0; j < 4; ++j)
#pragma unroll
            for (int q = 0; q < 4; ++q) d2[i][j][q] = 0.f;

    for (int it = 0; it < 16; ++it) {
        // ---- stage1: 4 planes into Z ----
#pragma unroll
        for (int pp = 0; pp < 4; ++pp) {
            int m01 = it * 4 + pp;
            uint32_t bfP[4];
            ldm_x4(bfP, sbu + P_OFF + SW((uint32_t)((m01 * 8 + lr) * 64 + quad * 16)));
            uint32_t zpb = ZX_OFF + (uint32_t)(pp * 32768);
#pragma unroll
            for (int mt = 0; mt < 16; ++mt) {
                float acc[4] = {0.f, 0.f, 0.f, 0.f};
                mma16816(acc, ac[mt][0], &bfP[0]);
                mma16816(acc, ac[mt][1], &bfP[2]);
                int Rb = w * 256 + mt * 16 + (lane >> 2);
#pragma unroll
                for (int half = 0; half < 2; ++half) {
                    int R = Rb + half * 8;
                    int n23 = R >> 6, bl = R & 63;
                    __half2 v = __floats2half2_rn(acc[half * 2], acc[half * 2 + 1]);
                    *(uint32_t*)(smem + zpb
                        + zsw(bl, (uint32_t)(n23 * 16 + (lane & 3) * 4))) = h2u(v);
                }
            }
        }
        __syncthreads();                            // Z ready

        // ---- stage2: warp tile 64(bl) x 32(m23) on plane plane_sel ----
        const uint32_t za = sbu + ZX_OFF + (uint32_t)(plane_sel * 32768);
#pragma unroll
        for (int ks = 0; ks < 16; ++ks) {
            uint32_t a[4][4], bq[2][4];
#pragma unroll
            for (int mt = 0; mt < 4; ++mt)
                ldm_x4(a[mt], za + zsw(mt * 16 + (lane & 15),
                                       (uint32_t)(ks * 32 + (lane >> 4) * 16)));
#pragma unroll
            for (int nt = 0; nt < 2; ++nt)
                ldm_x4(bq[nt], sbu + Q_OFF
                       + zsw(colhalf * 32 + nt * 16 + ((quad >> 1) & 1) * 8 + lr,
                             (uint32_t)(ks * 32 + (quad & 1) * 16)));
#pragma unroll
            for (int mt = 0; mt < 4; ++mt)
#pragma unroll
                for (int nt = 0; nt < 2; ++nt) {
                    mma16816(d2[mt][nt * 2],     a[mt], &bq[nt][0]);
                    mma16816(d2[mt][nt * 2 + 1], a[mt], &bq[nt][2]);
                }
        }

        // ---- epilogue: +bias, write fp32; reset accumulators ----
        const int m01 = it * 4 + plane_sel;
        const int ecolb = m01 * 64 + colhalf * 32 + (lane & 3) * 2;
#pragma unroll
        for (int mt = 0; mt < 4; ++mt) {
            const int erow = b0 + mt * 16 + (lane >> 2);
#pragma unroll
            for (int nt = 0; nt < 2; ++nt) {
#pragma unroll
                for (int p = 0; p < 2; ++p) {
                    int col = ecolb + nt * 16 + p * 8;
                    float bx = __ldg(bias + col);
                    float by = __ldg(bias + col + 1);
                    float* r0 = out + (size_t)erow * OUTF + col;
                    float* r1 = r0 + 8 * OUTF;
                    float* dd = d2[mt][nt * 2 + p];
                    float2 v0 = { dd[0] + bx, dd[1] + by };
                    float2 v1 = { dd[2] + bx, dd[3] + by };
                    *reinterpret_cast<float2*>(r0) = v0;
                    *reinterpret_cast<float2*>(r1) = v1;
                    dd[0] = dd[1] = dd[2] = dd[3] = 0.f;
                }
            }
        }
        __syncthreads();                            // Z reusable
    }
}

// ============================================================================
extern "C" void kernel_launch(void* const* d_in, const int* in_sizes, int n_in,
                              void* d_out, int out_size)
{
    const float* x    = (const float*)d_in[0];
    const float* c0   = (const float*)d_in[1];
    const float* c1   = (const float*)d_in[2];
    const float* c2   = (const float*)d_in[3];
    const float* c3   = (const float*)d_in[4];
    const float* bias = (const float*)d_in[5];
    float* out = (float*)d_out;

    cudaFuncSetAttribute(k_fused, cudaFuncAttributeMaxDynamicSharedMemorySize,
                         SMEM_TOTAL);
    k_fused<<<128, 256, SMEM_TOTAL>>>(x, c0, c1, c2, c3, bias, out);
}